// round 7
// baseline (speedup 1.0000x reference)
#include <cuda_runtime.h>
#include <cstdint>

#define CELL_F        30
#define TPB           128
#define NWARP         (TPB / 32)
#define WT_CELLS      32                       // cells per warp-tile
#define WT_FLOATS     (WT_CELLS * CELL_F)      // 960 per tensor
#define WT_F4         (WT_FLOATS / 4)          // 240
#define STAGE_FLOATS  (2 * WT_FLOATS)          // 1920  (p | g)
#define STAGE_BYTES   (STAGE_FLOATS * 4)       // 7680
#define WARP_FLOATS   (2 * STAGE_FLOATS)       // 3840 (2 stages)
#define SMEM_BYTES    (NWARP * WARP_FLOATS * 4)  // 61440
#define GRID_MAX      444                      // 3 blocks/SM * 148 SMs
#define MAX_TILES     16384

__device__ float        g_partials[MAX_TILES]; // per-tile partial sums (index-deterministic)
__device__ unsigned int g_count = 0;           // finished-block ticket
__device__ unsigned int g_tile  = 0;           // work-stealing cursor

__device__ __forceinline__ void cp_async16(uint32_t saddr, const void* gaddr) {
    asm volatile("cp.async.cg.shared.global [%0], [%1], 16;\n"
                 :: "r"(saddr), "l"(gaddr) : "memory");
}
__device__ __forceinline__ void cp_commit() {
    asm volatile("cp.async.commit_group;\n" ::: "memory");
}
__device__ __forceinline__ void cp_wait1() {
    asm volatile("cp.async.wait_group 1;\n" ::: "memory");
}

__device__ __forceinline__ float softp(float x) {      // log(1+e^x), |x| small
    return __logf(1.0f + __expf(x));
}
__device__ __forceinline__ float sigm(float x) {
    return __fdividef(1.0f, 1.0f + __expf(-x));
}
__device__ __forceinline__ float sqrt_ap(float x) {
    float r; asm("sqrt.approx.f32 %0, %1;" : "=f"(r) : "f"(x)); return r;
}
__device__ __forceinline__ float iou_f(float al, float at, float ar, float ab,
                                       float bl, float bt, float br, float bb,
                                       float area_a, float area_b) {
    float ltx = fmaxf(al, bl), lty = fmaxf(at, bt);
    float rbx = fminf(ar, br), rby = fminf(ab, bb);
    float wx = fmaxf(rbx - ltx, 0.0f), wy = fmaxf(rby - lty, 0.0f);
    float inter = wx * wy;
    return __fdividef(inter, area_a + area_b - inter + 1e-7f);
}

__global__ void __launch_bounds__(TPB)
k_main(const float* __restrict__ p, const float* __restrict__ g,
       int ncells, int ntiles, float* __restrict__ out, double inv_batch) {
    extern __shared__ float s[];              // [warp][stage][p:960|g:960]
    __shared__ double wdsum[TPB / 32];
    __shared__ unsigned int s_ticket;

    const int tid  = threadIdx.x;
    const int w    = tid >> 5;
    const int lane = tid & 31;
    float* swp = s + w * WARP_FLOATS;
    const uint32_t swb = (uint32_t)__cvta_generic_to_shared(swp);

    // ---- steal one tile index (warp-uniform) ----
    auto steal = [&]() -> int {
        unsigned int t = 0;
        if (lane == 0) t = atomicAdd(&g_tile, 1u);
        t = __shfl_sync(0xFFFFFFFFu, t, 0);
        return (int)t;
    };

    // ---- prefetch one warp-tile into a stage (always commits exactly one group) ----
    auto prefetch = [&](int stage, int t) {
        if (t < ntiles) {
            const float4* p4 = reinterpret_cast<const float4*>(p) + (long long)t * WT_F4;
            const float4* g4 = reinterpret_cast<const float4*>(g) + (long long)t * WT_F4;
            uint32_t sp_ = swb + (uint32_t)stage * STAGE_BYTES;
            uint32_t sg_ = sp_ + WT_FLOATS * 4;
            if ((t + 1) * WT_CELLS <= ncells) {
                #pragma unroll
                for (int k = 0; k < 8; k++) {
                    int i = lane + k * 32;
                    if (i < WT_F4) {
                        cp_async16(sp_ + i * 16, p4 + i);
                        cp_async16(sg_ + i * 16, g4 + i);
                    }
                }
            } else {            // ragged final tile: scalar staging
                int nf = (ncells - t * WT_CELLS) * CELL_F;
                float* sd = swp + stage * STAGE_FLOATS;
                const float* pb = p + (long long)t * WT_FLOATS;
                const float* gb = g + (long long)t * WT_FLOATS;
                for (int ff = lane; ff < nf; ff += 32) {
                    sd[ff]             = pb[ff];
                    sd[WT_FLOATS + ff] = gb[ff];
                }
            }
        }
        cp_commit();
    };

    int t_cur = steal();
    prefetch(0, t_cur);
    int t_nxt = steal();
    prefetch(1, t_nxt);

    int stage = 0;
    while (t_cur < ntiles) {
        int t_fut = steal();            // issued early: ~320cyc latency hides under compute
        cp_wait1();
        __syncwarp();

        const float* sb = swp + stage * STAGE_FLOATS;
        int cell = t_cur * WT_CELLS + lane;
        float loss = 0.0f;
        if (cell < ncells) {
            const float2* P2 = reinterpret_cast<const float2*>(sb) + lane * 15;
            const float2* G2 = reinterpret_cast<const float2*>(sb + WT_FLOATS) + lane * 15;

            float2 Pa = P2[0], Pb_ = P2[1], Pc = P2[2], Pd = P2[3], Pe = P2[4];
            float2 Ga = G2[0], Gb_ = G2[1], Gc = G2[2], Gd = G2[3], Ge = G2[4];
            float conf_g = Ge.x;

            // ---- class BCE via log of products (2 groups of 10) ----
            float pr0 = 1.0f, pr1 = 1.0f, spg = 0.0f;
            #pragma unroll
            for (int k = 5; k < 10; k++) {
                float2 pv = P2[k], gv = G2[k];
                pr0 *= (1.0f + __expf(pv.x)) * (1.0f + __expf(pv.y));
                spg += pv.x * gv.x + pv.y * gv.y;
            }
            #pragma unroll
            for (int k = 10; k < 15; k++) {
                float2 pv = P2[k], gv = G2[k];
                pr1 *= (1.0f + __expf(pv.x)) * (1.0f + __expf(pv.y));
                spg += pv.x * gv.x + pv.y * gv.y;
            }
            float cls = __logf(pr0) + __logf(pr1) - spg;

            int ij = cell % 49;
            int r  = ij / 7;
            int c  = ij - r * 7;
            float colf = (float)c, rowf = (float)r;

            float sx0 = sigm(Pa.x), sy0 = sigm(Pa.y), pw0 = Pb_.x, ph0 = Pb_.y;
            float sx1 = sigm(Pc.x), sy1 = sigm(Pc.y), pw1 = Pd.x,  ph1 = Pd.y;
            float gx0 = Ga.x, gy0 = Ga.y, gw0 = Gb_.x, gh0 = Gb_.y;
            float gx1 = Gc.x, gy1 = Gc.y, gw1 = Gd.x,  gh1 = Gd.y;

            // IoU in 7x-scaled coords (scale-invariant)
            float pcx0 = sx0 + colf, pcy0 = sy0 + rowf;
            float pcx1 = sx1 + colf, pcy1 = sy1 + rowf;
            float gcx0 = gx0 + colf, gcy0 = gy0 + rowf;
            float gcx1 = gx1 + colf, gcy1 = gy1 + rowf;
            const float H = 3.5f;

            float pl0 = pcx0 - pw0 * H, pt0 = pcy0 - ph0 * H;
            float pr_0 = pcx0 + pw0 * H, pb0 = pcy0 + ph0 * H;
            float pl1 = pcx1 - pw1 * H, pt1 = pcy1 - ph1 * H;
            float pr_1 = pcx1 + pw1 * H, pb1 = pcy1 + ph1 * H;
            float gl0 = gcx0 - gw0 * H, gt0 = gcy0 - gh0 * H;
            float gr0 = gcx0 + gw0 * H, gb0 = gcy0 + gh0 * H;
            float gl1 = gcx1 - gw1 * H, gt1 = gcy1 - gh1 * H;
            float gr1 = gcx1 + gw1 * H, gb1 = gcy1 + gh1 * H;

            float ap0 = (pr_0 - pl0) * (pb0 - pt0);
            float ap1 = (pr_1 - pl1) * (pb1 - pt1);
            float ag0 = (gr0 - gl0) * (gb0 - gt0);
            float ag1 = (gr1 - gl1) * (gb1 - gt1);

            float i00 = iou_f(pl0, pt0, pr_0, pb0, gl0, gt0, gr0, gb0, ap0, ag0);
            float i10 = iou_f(pl1, pt1, pr_1, pb1, gl0, gt0, gr0, gb0, ap1, ag0);
            float i01 = iou_f(pl0, pt0, pr_0, pb0, gl1, gt1, gr1, gb1, ap0, ag1);
            float i11 = iou_f(pl1, pt1, pr_1, pb1, gl1, gt1, gr1, gb1, ap1, ag1);

            bool ind0 = i10 > i00;     // jnp.argmax: first max wins
            bool ind1 = i11 > i01;

            bool same_g   = (gx0 == gx1) && (gy0 == gy1) && (gw0 == gw1) && (gh0 == gh1);
            bool same_ind = (ind0 == ind1);

            float sqw0 = sqrt_ap(fabsf(pw0)), sqh0 = sqrt_ap(fabsf(ph0));
            float sqw1 = sqrt_ap(fabsf(pw1)), sqh1 = sqrt_ap(fabsf(ph1));
            float sgw0 = sqrt_ap(gw0), sgh0 = sqrt_ap(gh0);
            float sgw1 = sqrt_ap(gw1), sgh1 = sqrt_ap(gh1);

            #define BLOSS(px, py, qw, qh, qx, qy, rw, rh)                         \
                ((px - qx) * (px - qx) + (py - qy) * (py - qy) +                  \
                 (qw - rw) * (qw - rw) + (qh - rh) * (qh - rh))
            float l00 = BLOSS(sx0, sy0, sqw0, sqh0, gx0, gy0, sgw0, sgh0);
            float l10 = BLOSS(sx1, sy1, sqw1, sqh1, gx0, gy0, sgw0, sgh0);
            float l01 = BLOSS(sx0, sy0, sqw0, sqh0, gx1, gy1, sgw1, sgh1);
            float l11 = BLOSS(sx1, sy1, sqw1, sqh1, gx1, gy1, sgw1, sgh1);
            #undef BLOSS

            float lA = ind0 ? l10 : l00;
            float lB = l00 + l11;
            float lC = lA + (ind1 ? l11 : l01);
            float box_cell = same_g ? lA : (same_ind ? lB : lC);

            float pc0 = Pe.x, pc1 = Pe.y;
            float sp8 = softp(pc0), sp9 = softp(pc1);
            float confA  = ind1 ? (sp9 - pc1) : (sp8 - pc0);
            float confBC = (sp8 - pc0) + (sp9 - pc1);
            float conf_cell = same_g ? confA : confBC;

            float lossP = 5.0f * box_cell + conf_cell + cls;
            float lossN = 0.5f * (sp8 + sp9);
            loss = (conf_g > 0.0f) ? lossP : ((conf_g == 0.0f) ? lossN : 0.0f);
        }

        // per-tile warp reduction -> deterministic per-tile slot
        #pragma unroll
        for (int o = 16; o > 0; o >>= 1) loss += __shfl_xor_sync(0xFFFFFFFFu, loss, o);
        if (lane == 0) g_partials[t_cur] = loss;

        __syncwarp();
        prefetch(stage, t_fut);
        stage ^= 1;
        t_cur = t_nxt;
        t_nxt = t_fut;
    }

    // ---------- make partials visible, then ticket ----------
    __threadfence();
    __syncthreads();
    if (tid == 0) s_ticket = atomicAdd(&g_count, 1u);
    __syncthreads();

    // ---------- last block finalizes (fixed-order double sum => deterministic) ----------
    if (s_ticket == gridDim.x - 1) {
        __threadfence();                       // acquire: see all partials
        volatile float* vp = g_partials;
        double dacc = 0.0;
        for (int i = tid; i < ntiles; i += TPB) dacc += (double)vp[i];
        #pragma unroll
        for (int o = 16; o > 0; o >>= 1) dacc += __shfl_xor_sync(0xFFFFFFFFu, dacc, o);
        if ((tid & 31) == 0) wdsum[tid >> 5] = dacc;
        __syncthreads();
        if (tid == 0) {
            double tot = 0.0;
            #pragma unroll
            for (int ww = 0; ww < TPB / 32; ww++) tot += wdsum[ww];
            *out = (float)(tot * inv_batch);
            g_count = 0;                       // restore for next graph replay
            g_tile  = 0;
        }
    }
}

extern "C" void kernel_launch(void* const* d_in, const int* in_sizes, int n_in,
                              void* d_out, int out_size) {
    const float* p = (const float*)d_in[0];
    const float* g = (const float*)d_in[1];
    int total  = in_sizes[0];            // B*7*7*30
    int ncells = total / CELL_F;         // B*49
    int batch  = ncells / 49;
    int ntiles = (ncells + WT_CELLS - 1) / WT_CELLS;
    int nb = GRID_MAX;
    int nb_need = (ntiles + 2 * NWARP - 1) / (2 * NWARP);
    if (nb > nb_need) nb = nb_need;
    if (nb < 1) nb = 1;

    static int attr_set = 0;
    if (!attr_set) {
        cudaFuncSetAttribute(k_main, cudaFuncAttributeMaxDynamicSharedMemorySize, SMEM_BYTES);
        attr_set = 1;
    }
    k_main<<<nb, TPB, SMEM_BYTES>>>(p, g, ncells, ntiles, (float*)d_out, 1.0 / (double)batch);
}

// round 8
// speedup vs baseline: 1.4100x; 1.4100x over previous
#include <cuda_runtime.h>
#include <cstdint>

#define CELL_F    30
#define TPB       128
#define NWARP     (TPB / 32)
#define WT        32                        // cells per warp-tile
#define HEAD_B    48                        // staged bytes per cell per tensor (floats 0..11)
#define STAGE_B   (2 * WT * HEAD_B)         // 3072  (p-head | g-head)
#define WARP_B    (2 * STAGE_B)             // 6144  (2 stages)
#define SMEM_B    (NWARP * WARP_B)          // 24576 per block
#define GRID_MAX  1332                      // 9 blocks/SM * 148 SMs

__device__ float        g_partials[2048];
__device__ unsigned int g_count = 0;

__device__ __forceinline__ void cp_async8(uint32_t saddr, const void* gaddr) {
    asm volatile("cp.async.ca.shared.global [%0], [%1], 8;\n"
                 :: "r"(saddr), "l"(gaddr) : "memory");
}
__device__ __forceinline__ void cp_commit() {
    asm volatile("cp.async.commit_group;\n" ::: "memory");
}
__device__ __forceinline__ void cp_wait1() {
    asm volatile("cp.async.wait_group 1;\n" ::: "memory");
}

__device__ __forceinline__ float softp(float x) {      // log(1+e^x), |x| small
    return __logf(1.0f + __expf(x));
}
__device__ __forceinline__ float sigm(float x) {
    return __fdividef(1.0f, 1.0f + __expf(-x));
}
__device__ __forceinline__ float sqrt_ap(float x) {
    float r; asm("sqrt.approx.f32 %0, %1;" : "=f"(r) : "f"(x)); return r;
}
__device__ __forceinline__ float iou_f(float al, float at, float ar, float ab,
                                       float bl, float bt, float br, float bb,
                                       float area_a, float area_b) {
    float ltx = fmaxf(al, bl), lty = fmaxf(at, bt);
    float rbx = fminf(ar, br), rby = fminf(ab, bb);
    float wx = fmaxf(rbx - ltx, 0.0f), wy = fmaxf(rby - lty, 0.0f);
    float inter = wx * wy;
    return __fdividef(inter, area_a + area_b - inter + 1e-7f);
}

__global__ void __launch_bounds__(TPB, 8)
k_main(const float* __restrict__ p, const float* __restrict__ g,
       int ncells, int ntiles, float* __restrict__ out, double inv_batch) {
    extern __shared__ float s[];               // [warp][stage][p-head 1536B | g-head 1536B]
    __shared__ float wsum[NWARP];
    __shared__ double wdsum[TPB / 32];
    __shared__ unsigned int s_ticket;

    const int tid  = threadIdx.x;
    const int w    = tid >> 5;
    const int lane = tid & 31;
    float* swp = s + w * (WARP_B / 4);
    const uint32_t swb = (uint32_t)__cvta_generic_to_shared(swp);

    const int S  = gridDim.x * NWARP;          // warp-streams
    const int ws = blockIdx.x * NWARP + w;

    // per-lane start indices for the two flat walks
    const int hc0 = lane / 6,  hch0 = lane - 6 * hc0;      // head chunks: 6 x 8B per cell
    const int cc0 = lane / 9,  ce0  = lane - 9 * cc0;      // cls pairs:   9 x 8B per cell

    // ---- prefetch head (48B/cell/tensor) of one tile into a stage ----
    auto prefetch = [&](int stage, int t) {
        if (t < ntiles) {
            int nv = ncells - t * WT; if (nv > WT) nv = WT;
            const ulonglong1* p8 = reinterpret_cast<const ulonglong1*>(p) + (long long)t * (WT * 15);
            const ulonglong1* g8 = reinterpret_cast<const ulonglong1*>(g) + (long long)t * (WT * 15);
            uint32_t sp_ = swb + (uint32_t)stage * STAGE_B;
            uint32_t sg_ = sp_ + WT * HEAD_B;
            int cc = hc0, ch = hch0;
            #pragma unroll
            for (int k = 0; k < 6; k++) {
                if (cc < nv) {
                    int gi = cc * 15 + ch;                 // 8B units within tile
                    uint32_t so = (uint32_t)(cc * HEAD_B + ch * 8);
                    cp_async8(sp_ + so, p8 + gi);
                    cp_async8(sg_ + so, g8 + gi);
                }
                cc += 5; ch += 2; if (ch >= 6) { ch -= 6; cc += 1; }
            }
        }
        cp_commit();
    };

    prefetch(0, ws);
    prefetch(1, ws + S);

    float acc = 0.0f;
    int it = 0;
    for (int t = ws; t < ntiles; t += S, it++) {
        cp_wait1();
        __syncwarp();

        const int stage = it & 1;
        float* st = swp + stage * (STAGE_B / 4);           // p-head floats
        float* gh = st + (WT * HEAD_B / 4);                // g-head floats (12 per cell)
        int nv = ncells - t * WT; if (nv > WT) nv = WT;

        float facc0 = 1.0f, facc1 = 1.0f, dacc = 0.0f;

        // ================= per-cell head phase (own cell = t*WT + lane) =================
        {
            bool valid = lane < nv;
            int ci = valid ? lane : 0;
            const float4* P4 = reinterpret_cast<const float4*>(st) + ci * 3;
            const float4* G4 = reinterpret_cast<const float4*>(gh) + ci * 3;
            float4 F0 = P4[0], F1 = P4[1], F2 = P4[2];
            float4 H0 = G4[0], H1 = G4[1], H2 = G4[2];

            float conf_g = H2.x;
            bool pos  = valid && (conf_g > 0.0f);
            bool zero = valid && (conf_g == 0.0f);

            // fold own cls elements 10,11 into the masked product chains
            facc0 *= pos ? (1.0f + __expf(F2.z)) : 1.0f;
            facc1 *= pos ? (1.0f + __expf(F2.w)) : 1.0f;
            dacc  += pos ? (F2.z * H2.z + F2.w * H2.w) : 0.0f;

            int cell = t * WT + lane;
            int ij = cell % 49;
            int r  = ij / 7;
            int c  = ij - r * 7;
            float colf = (float)c, rowf = (float)r;

            float sx0 = sigm(F0.x), sy0 = sigm(F0.y), pw0 = F0.z, ph0 = F0.w;
            float sx1 = sigm(F1.x), sy1 = sigm(F1.y), pw1 = F1.z, ph1 = F1.w;
            float gx0 = H0.x, gy0 = H0.y, gw0 = H0.z, gh0 = H0.w;
            float gx1 = H1.x, gy1 = H1.y, gw1 = H1.z, gh1 = H1.w;

            // IoU in 7x-scaled coords (scale-invariant)
            float pcx0 = sx0 + colf, pcy0 = sy0 + rowf;
            float pcx1 = sx1 + colf, pcy1 = sy1 + rowf;
            float gcx0 = gx0 + colf, gcy0 = gy0 + rowf;
            float gcx1 = gx1 + colf, gcy1 = gy1 + rowf;
            const float HF = 3.5f;

            float pl0 = pcx0 - pw0 * HF, pt0 = pcy0 - ph0 * HF;
            float pr_0 = pcx0 + pw0 * HF, pb0 = pcy0 + ph0 * HF;
            float pl1 = pcx1 - pw1 * HF, pt1 = pcy1 - ph1 * HF;
            float pr_1 = pcx1 + pw1 * HF, pb1 = pcy1 + ph1 * HF;
            float gl0 = gcx0 - gw0 * HF, gt0 = gcy0 - gh0 * HF;
            float gr0 = gcx0 + gw0 * HF, gb0 = gcy0 + gh0 * HF;
            float gl1 = gcx1 - gw1 * HF, gt1 = gcy1 - gh1 * HF;
            float gr1 = gcx1 + gw1 * HF, gb1 = gcy1 + gh1 * HF;

            float ap0 = (pr_0 - pl0) * (pb0 - pt0);
            float ap1 = (pr_1 - pl1) * (pb1 - pt1);
            float ag0 = (gr0 - gl0) * (gb0 - gt0);
            float ag1 = (gr1 - gl1) * (gb1 - gt1);

            float i00 = iou_f(pl0, pt0, pr_0, pb0, gl0, gt0, gr0, gb0, ap0, ag0);
            float i10 = iou_f(pl1, pt1, pr_1, pb1, gl0, gt0, gr0, gb0, ap1, ag0);
            float i01 = iou_f(pl0, pt0, pr_0, pb0, gl1, gt1, gr1, gb1, ap0, ag1);
            float i11 = iou_f(pl1, pt1, pr_1, pb1, gl1, gt1, gr1, gb1, ap1, ag1);

            bool ind0 = i10 > i00;     // jnp.argmax: first max wins
            bool ind1 = i11 > i01;

            bool same_g   = (gx0 == gx1) && (gy0 == gy1) && (gw0 == gw1) && (gh0 == gh1);
            bool same_ind = (ind0 == ind1);

            float sqw0 = sqrt_ap(fabsf(pw0)), sqh0 = sqrt_ap(fabsf(ph0));
            float sqw1 = sqrt_ap(fabsf(pw1)), sqh1 = sqrt_ap(fabsf(ph1));
            float sgw0 = sqrt_ap(gw0), sgh0 = sqrt_ap(gh0);
            float sgw1 = sqrt_ap(gw1), sgh1 = sqrt_ap(gh1);

            #define BLOSS(px, py, qw, qh, qx, qy, rw, rh)                         \
                ((px - qx) * (px - qx) + (py - qy) * (py - qy) +                  \
                 (qw - rw) * (qw - rw) + (qh - rh) * (qh - rh))
            float l00 = BLOSS(sx0, sy0, sqw0, sqh0, gx0, gy0, sgw0, sgh0);
            float l10 = BLOSS(sx1, sy1, sqw1, sqh1, gx0, gy0, sgw0, sgh0);
            float l01 = BLOSS(sx0, sy0, sqw0, sqh0, gx1, gy1, sgw1, sgh1);
            float l11 = BLOSS(sx1, sy1, sqw1, sqh1, gx1, gy1, sgw1, sgh1);
            #undef BLOSS

            float lA = ind0 ? l10 : l00;
            float lB = l00 + l11;
            float lC = lA + (ind1 ? l11 : l01);
            float box_cell = same_g ? lA : (same_ind ? lB : lC);

            float pc0 = F2.x, pc1 = F2.y;
            float sp8 = softp(pc0), sp9 = softp(pc1);
            float confA  = ind1 ? (sp9 - pc1) : (sp8 - pc0);
            float confBC = (sp8 - pc0) + (sp9 - pc1);
            float conf_cell = same_g ? confA : confBC;

            float lossP = 5.0f * box_cell + conf_cell;     // cls handled via facc/dacc
            float lossN = 0.5f * (sp8 + sp9);
            acc += pos ? lossP : (zero ? lossN : 0.0f);
        }

        // ====== coalesced cls phase: floats 12..29 of every cell (9 float2 x 2 tensors) ======
        {
            const float2* Pc2 = reinterpret_cast<const float2*>(p) + (long long)t * (WT * 15);
            const float2* Gc2 = reinterpret_cast<const float2*>(g) + (long long)t * (WT * 15);
            int cc = cc0, e = ce0;
            #pragma unroll
            for (int k = 0; k < 9; k++) {
                bool ok = cc < nv;
                int ci = ok ? cc : 0;
                int idx = ci * 15 + 6 + e;
                float2 pv = Pc2[idx];
                float2 gv = Gc2[idx];
                float conf = gh[ci * 12 + 8];
                bool m = ok && (conf > 0.0f);
                float f2 = (1.0f + __expf(pv.x)) * (1.0f + __expf(pv.y));
                if (k & 1) facc1 *= m ? f2 : 1.0f;
                else       facc0 *= m ? f2 : 1.0f;
                dacc += m ? (pv.x * gv.x + pv.y * gv.y) : 0.0f;
                cc += 3; e += 5; if (e >= 9) { e -= 9; cc += 1; }
            }
        }
        acc += __logf(facc0) + __logf(facc1) - dacc;

        __syncwarp();                    // warp done reading this stage
        prefetch(stage, t + 2 * S);      // exactly one commit
    }

    // ---------- block reduction (once per block) ----------
    float loss = acc;
    #pragma unroll
    for (int o = 16; o > 0; o >>= 1) loss += __shfl_xor_sync(0xFFFFFFFFu, loss, o);
    if (lane == 0) wsum[w] = loss;
    __syncthreads();
    if (tid == 0) {
        float bs = 0.0f;
        #pragma unroll
        for (int ww = 0; ww < NWARP; ww++) bs += wsum[ww];
        g_partials[blockIdx.x] = bs;
        __threadfence();
        s_ticket = atomicAdd(&g_count, 1u);
    }
    __syncthreads();

    // ---------- last block finalizes (fixed-order double sum; self-resetting; graph-safe) ----------
    if (s_ticket == gridDim.x - 1) {
        __threadfence();
        volatile float* vp = g_partials;
        double dacc = 0.0;
        for (int i = tid; i < (int)gridDim.x; i += TPB) dacc += (double)vp[i];
        #pragma unroll
        for (int o = 16; o > 0; o >>= 1) dacc += __shfl_xor_sync(0xFFFFFFFFu, dacc, o);
        if ((tid & 31) == 0) wdsum[tid >> 5] = dacc;
        __syncthreads();
        if (tid == 0) {
            double tot = 0.0;
            #pragma unroll
            for (int ww = 0; ww < TPB / 32; ww++) tot += wdsum[ww];
            *out = (float)(tot * inv_batch);
            g_count = 0;                 // restore for next graph replay
        }
    }
}

extern "C" void kernel_launch(void* const* d_in, const int* in_sizes, int n_in,
                              void* d_out, int out_size) {
    const float* p = (const float*)d_in[0];
    const float* g = (const float*)d_in[1];
    int total  = in_sizes[0];            // B*7*7*30
    int ncells = total / CELL_F;         // B*49
    int batch  = ncells / 49;
    int ntiles = (ncells + WT - 1) / WT;
    int nb = GRID_MAX;
    int nb_need = (ntiles + NWARP - 1) / NWARP;
    if (nb > nb_need) nb = nb_need;
    if (nb < 1) nb = 1;

    k_main<<<nb, TPB, SMEM_B>>>(p, g, ncells, ntiles, (float*)d_out, 1.0 / (double)batch);
}

// round 9
// speedup vs baseline: 1.7358x; 1.2311x over previous
#include <cuda_runtime.h>
#include <cstdint>

#define CELL_F        30
#define TPB           128
#define NWARP         (TPB / 32)
#define WT_CELLS      32                       // cells per warp-tile
#define WT_FLOATS     (WT_CELLS * CELL_F)      // 960 per tensor
#define WT_F4         (WT_FLOATS / 4)          // 240
#define WT_BYTES      (WT_FLOATS * 4)          // 3840 per tensor (30 x 128B lines)
#define STAGE_FLOATS  (2 * WT_FLOATS)          // 1920  (p | g)
#define STAGE_BYTES   (STAGE_FLOATS * 4)       // 7680
#define WARP_FLOATS   (2 * STAGE_FLOATS)       // 3840 (2 stages)
#define SMEM_BYTES    (NWARP * WARP_FLOATS * 4)  // 61440
#define GRID_MAX      444                      // 3 blocks/SM * 148 SMs

__device__ float        g_partials[GRID_MAX];
__device__ unsigned int g_count = 0;

__device__ __forceinline__ void cp_async16(uint32_t saddr, const void* gaddr) {
    asm volatile("cp.async.cg.shared.global [%0], [%1], 16;\n"
                 :: "r"(saddr), "l"(gaddr) : "memory");
}
__device__ __forceinline__ void cp_commit() {
    asm volatile("cp.async.commit_group;\n" ::: "memory");
}
__device__ __forceinline__ void cp_wait1() {
    asm volatile("cp.async.wait_group 1;\n" ::: "memory");
}
__device__ __forceinline__ void l2_prefetch(const void* gaddr) {
    asm volatile("prefetch.global.L2 [%0];" :: "l"(gaddr));
}

__device__ __forceinline__ float softp(float x) {      // log(1+e^x), |x| small
    return __logf(1.0f + __expf(x));
}
__device__ __forceinline__ float sigm(float x) {
    return __fdividef(1.0f, 1.0f + __expf(-x));
}
__device__ __forceinline__ float sqrt_ap(float x) {
    float r; asm("sqrt.approx.f32 %0, %1;" : "=f"(r) : "f"(x)); return r;
}
__device__ __forceinline__ float iou_f(float al, float at, float ar, float ab,
                                       float bl, float bt, float br, float bb,
                                       float area_a, float area_b) {
    float ltx = fmaxf(al, bl), lty = fmaxf(at, bt);
    float rbx = fminf(ar, br), rby = fminf(ab, bb);
    float wx = fmaxf(rbx - ltx, 0.0f), wy = fmaxf(rby - lty, 0.0f);
    float inter = wx * wy;
    return __fdividef(inter, area_a + area_b - inter + 1e-7f);
}

__global__ void __launch_bounds__(TPB)
k_main(const float* __restrict__ p, const float* __restrict__ g,
       int ncells, int ntiles, float* __restrict__ out, double inv_batch) {
    extern __shared__ float s[];              // [warp][stage][p:960|g:960]
    __shared__ float wsum[NWARP];
    __shared__ double wdsum[TPB / 32];
    __shared__ unsigned int s_ticket;

    const int tid  = threadIdx.x;
    const int w    = tid >> 5;
    const int lane = tid & 31;
    float* swp = s + w * WARP_FLOATS;         // this warp's 2-stage buffer
    const uint32_t swb = (uint32_t)__cvta_generic_to_shared(swp);

    const int S  = gridDim.x * NWARP;         // warp-streams
    const int ws = blockIdx.x * NWARP + w;

    // ---- fire-and-forget L2 prefetch of one tile (30 lines per tensor) ----
    auto l2pf = [&](int t) {
        if (t < ntiles && lane < 30) {
            const char* pc = reinterpret_cast<const char*>(p) + (long long)t * WT_BYTES + lane * 128;
            const char* gc = reinterpret_cast<const char*>(g) + (long long)t * WT_BYTES + lane * 128;
            l2_prefetch(pc);
            l2_prefetch(gc);
        }
    };

    // ---- prefetch one warp-tile into a stage (always commits exactly one group) ----
    auto prefetch = [&](int stage, int t) {
        if (t < ntiles) {
            const float4* p4 = reinterpret_cast<const float4*>(p) + (long long)t * WT_F4;
            const float4* g4 = reinterpret_cast<const float4*>(g) + (long long)t * WT_F4;
            uint32_t sp_ = swb + (uint32_t)stage * STAGE_BYTES;
            uint32_t sg_ = sp_ + WT_FLOATS * 4;
            if ((t + 1) * WT_CELLS <= ncells) {
                #pragma unroll
                for (int k = 0; k < 8; k++) {
                    int i = lane + k * 32;
                    if (i < WT_F4) {
                        cp_async16(sp_ + i * 16, p4 + i);
                        cp_async16(sg_ + i * 16, g4 + i);
                    }
                }
            } else {            // ragged final tile: scalar staging
                int nf = (ncells - t * WT_CELLS) * CELL_F;
                float* sd = swp + stage * STAGE_FLOATS;
                const float* pb = p + (long long)t * WT_FLOATS;
                const float* gb = g + (long long)t * WT_FLOATS;
                for (int ff = lane; ff < nf; ff += 32) {
                    sd[ff]             = pb[ff];
                    sd[WT_FLOATS + ff] = gb[ff];
                }
            }
        }
        cp_commit();
    };

    l2pf(ws + 2 * S);                         // warm L2 ahead of the first refills
    prefetch(0, ws);
    prefetch(1, ws + S);

    float acc = 0.0f;
    int it = 0;
    for (int t = ws; t < ntiles; t += S, it++) {
        l2pf(t + 3 * S);                      // DRAM pipeline: 3 rounds ahead, each line once
        cp_wait1();
        __syncwarp();

        const float* sb = swp + (it & 1) * STAGE_FLOATS;
        int cell = t * WT_CELLS + lane;
        if (cell < ncells) {
            const float2* P2 = reinterpret_cast<const float2*>(sb) + lane * 15;
            const float2* G2 = reinterpret_cast<const float2*>(sb + WT_FLOATS) + lane * 15;

            float2 Pa = P2[0], Pb_ = P2[1], Pc = P2[2], Pd = P2[3], Pe = P2[4];
            float2 Ga = G2[0], Gb_ = G2[1], Gc = G2[2], Gd = G2[3], Ge = G2[4];
            float conf_g = Ge.x;

            // ---- class BCE via log of products (2 groups of 10) ----
            float pr0 = 1.0f, pr1 = 1.0f, spg = 0.0f;
            #pragma unroll
            for (int k = 5; k < 10; k++) {
                float2 pv = P2[k], gv = G2[k];
                pr0 *= (1.0f + __expf(pv.x)) * (1.0f + __expf(pv.y));
                spg += pv.x * gv.x + pv.y * gv.y;
            }
            #pragma unroll
            for (int k = 10; k < 15; k++) {
                float2 pv = P2[k], gv = G2[k];
                pr1 *= (1.0f + __expf(pv.x)) * (1.0f + __expf(pv.y));
                spg += pv.x * gv.x + pv.y * gv.y;
            }
            float cls = __logf(pr0) + __logf(pr1) - spg;

            int ij = cell % 49;
            int r  = ij / 7;
            int c  = ij - r * 7;
            float colf = (float)c, rowf = (float)r;

            float sx0 = sigm(Pa.x), sy0 = sigm(Pa.y), pw0 = Pb_.x, ph0 = Pb_.y;
            float sx1 = sigm(Pc.x), sy1 = sigm(Pc.y), pw1 = Pd.x,  ph1 = Pd.y;
            float gx0 = Ga.x, gy0 = Ga.y, gw0 = Gb_.x, gh0 = Gb_.y;
            float gx1 = Gc.x, gy1 = Gc.y, gw1 = Gd.x,  gh1 = Gd.y;

            // IoU in 7x-scaled coords (scale-invariant)
            float pcx0 = sx0 + colf, pcy0 = sy0 + rowf;
            float pcx1 = sx1 + colf, pcy1 = sy1 + rowf;
            float gcx0 = gx0 + colf, gcy0 = gy0 + rowf;
            float gcx1 = gx1 + colf, gcy1 = gy1 + rowf;
            const float H = 3.5f;

            float pl0 = pcx0 - pw0 * H, pt0 = pcy0 - ph0 * H;
            float pr_0 = pcx0 + pw0 * H, pb0 = pcy0 + ph0 * H;
            float pl1 = pcx1 - pw1 * H, pt1 = pcy1 - ph1 * H;
            float pr_1 = pcx1 + pw1 * H, pb1 = pcy1 + ph1 * H;
            float gl0 = gcx0 - gw0 * H, gt0 = gcy0 - gh0 * H;
            float gr0 = gcx0 + gw0 * H, gb0 = gcy0 + gh0 * H;
            float gl1 = gcx1 - gw1 * H, gt1 = gcy1 - gh1 * H;
            float gr1 = gcx1 + gw1 * H, gb1 = gcy1 + gh1 * H;

            float ap0 = (pr_0 - pl0) * (pb0 - pt0);
            float ap1 = (pr_1 - pl1) * (pb1 - pt1);
            float ag0 = (gr0 - gl0) * (gb0 - gt0);
            float ag1 = (gr1 - gl1) * (gb1 - gt1);

            float i00 = iou_f(pl0, pt0, pr_0, pb0, gl0, gt0, gr0, gb0, ap0, ag0);
            float i10 = iou_f(pl1, pt1, pr_1, pb1, gl0, gt0, gr0, gb0, ap1, ag0);
            float i01 = iou_f(pl0, pt0, pr_0, pb0, gl1, gt1, gr1, gb1, ap0, ag1);
            float i11 = iou_f(pl1, pt1, pr_1, pb1, gl1, gt1, gr1, gb1, ap1, ag1);

            bool ind0 = i10 > i00;     // jnp.argmax: first max wins
            bool ind1 = i11 > i01;

            bool same_g   = (gx0 == gx1) && (gy0 == gy1) && (gw0 == gw1) && (gh0 == gh1);
            bool same_ind = (ind0 == ind1);

            float sqw0 = sqrt_ap(fabsf(pw0)), sqh0 = sqrt_ap(fabsf(ph0));
            float sqw1 = sqrt_ap(fabsf(pw1)), sqh1 = sqrt_ap(fabsf(ph1));
            float sgw0 = sqrt_ap(gw0), sgh0 = sqrt_ap(gh0);
            float sgw1 = sqrt_ap(gw1), sgh1 = sqrt_ap(gh1);

            #define BLOSS(px, py, qw, qh, qx, qy, rw, rh)                         \
                ((px - qx) * (px - qx) + (py - qy) * (py - qy) +                  \
                 (qw - rw) * (qw - rw) + (qh - rh) * (qh - rh))
            float l00 = BLOSS(sx0, sy0, sqw0, sqh0, gx0, gy0, sgw0, sgh0);
            float l10 = BLOSS(sx1, sy1, sqw1, sqh1, gx0, gy0, sgw0, sgh0);
            float l01 = BLOSS(sx0, sy0, sqw0, sqh0, gx1, gy1, sgw1, sgh1);
            float l11 = BLOSS(sx1, sy1, sqw1, sqh1, gx1, gy1, sgw1, sgh1);
            #undef BLOSS

            float lA = ind0 ? l10 : l00;
            float lB = l00 + l11;
            float lC = lA + (ind1 ? l11 : l01);
            float box_cell = same_g ? lA : (same_ind ? lB : lC);

            float pc0 = Pe.x, pc1 = Pe.y;
            float sp8 = softp(pc0), sp9 = softp(pc1);
            float confA  = ind1 ? (sp9 - pc1) : (sp8 - pc0);
            float confBC = (sp8 - pc0) + (sp9 - pc1);
            float conf_cell = same_g ? confA : confBC;

            float lossP = 5.0f * box_cell + conf_cell + cls;
            float lossN = 0.5f * (sp8 + sp9);
            acc += (conf_g > 0.0f) ? lossP : ((conf_g == 0.0f) ? lossN : 0.0f);
        }

        __syncwarp();                    // warp done reading this stage
        prefetch(it & 1, t + 2 * S);     // exactly one commit
    }

    // ---------- block reduction (once per block) ----------
    float loss = acc;
    #pragma unroll
    for (int o = 16; o > 0; o >>= 1) loss += __shfl_xor_sync(0xFFFFFFFFu, loss, o);
    if (lane == 0) wsum[w] = loss;
    __syncthreads();
    if (tid == 0) {
        float bs = 0.0f;
        #pragma unroll
        for (int ww = 0; ww < NWARP; ww++) bs += wsum[ww];
        g_partials[blockIdx.x] = bs;
        __threadfence();
        s_ticket = atomicAdd(&g_count, 1u);
    }
    __syncthreads();

    // ---------- last block finalizes (self-resetting counter; graph-safe) ----------
    if (s_ticket == gridDim.x - 1) {
        __threadfence();
        volatile float* vp = g_partials;
        double dacc = 0.0;
        for (int i = tid; i < (int)gridDim.x; i += TPB) dacc += (double)vp[i];
        #pragma unroll
        for (int o = 16; o > 0; o >>= 1) dacc += __shfl_xor_sync(0xFFFFFFFFu, dacc, o);
        if ((tid & 31) == 0) wdsum[tid >> 5] = dacc;
        __syncthreads();
        if (tid == 0) {
            double tot = 0.0;
            #pragma unroll
            for (int ww = 0; ww < TPB / 32; ww++) tot += wdsum[ww];
            *out = (float)(tot * inv_batch);
            g_count = 0;                 // restore for next graph replay
        }
    }
}

extern "C" void kernel_launch(void* const* d_in, const int* in_sizes, int n_in,
                              void* d_out, int out_size) {
    const float* p = (const float*)d_in[0];
    const float* g = (const float*)d_in[1];
    int total  = in_sizes[0];            // B*7*7*30
    int ncells = total / CELL_F;         // B*49
    int batch  = ncells / 49;
    int ntiles = (ncells + WT_CELLS - 1) / WT_CELLS;   // warp-tiles of 32 cells
    int nstreams_needed = (ntiles + 1) / 2;            // at least 1 tile per 2 stages
    int nb = GRID_MAX;
    if (nb * NWARP > nstreams_needed) {
        nb = (nstreams_needed + NWARP - 1) / NWARP;
        if (nb < 1) nb = 1;
    }

    static int attr_set = 0;
    if (!attr_set) {
        cudaFuncSetAttribute(k_main, cudaFuncAttributeMaxDynamicSharedMemorySize, SMEM_BYTES);
        attr_set = 1;
    }
    k_main<<<nb, TPB, SMEM_BYTES>>>(p, g, ncells, ntiles, (float*)d_out, 1.0 / (double)batch);
}